// round 1
// baseline (speedup 1.0000x reference)
#include <cuda_runtime.h>
#include <math.h>

#define NPOS 4096
#define QK_SCALE 0.2041241452319315f  /* 24^-0.5 */

// Scratch (device globals — no allocation allowed)
__device__ float g_buf1[576 * NPOS];   // qkv after 1x1 conv
__device__ float g_buf2[576 * NPOS];   // qkv after depthwise conv (q,k normalized in place)
__device__ float g_attn[192 * NPOS];   // attention output, [c][p] layout

// ---------------------------------------------------------------------------
// Pointwise (1x1) conv as GEMM: out[o][p] = sum_c w[o*IC+c] * in[c][p]
// Tile 64(O) x 64(P), 256 threads, 4x4 per thread, k-tile 16.
// ---------------------------------------------------------------------------
__global__ __launch_bounds__(256) void pw_conv_kernel(
    float* __restrict__ out, const float* __restrict__ in,
    const float* __restrict__ w, int IC)
{
    __shared__ __align__(16) float ws[16][65];  // [ck][oo], padded vs bank conflicts
    __shared__ __align__(16) float xs[16][64];  // [ck][pp]

    const int tid = threadIdx.x;
    const int tx = tid & 15, ty = tid >> 4;
    const int p0 = blockIdx.x * 64;
    const int o0 = blockIdx.y * 64;

    float acc[4][4] = {};

    for (int c0 = 0; c0 < IC; c0 += 16) {
        __syncthreads();
#pragma unroll
        for (int i = 0; i < 4; i++) {
            int e = tid + i * 256;            // 1024 elems
            int oo = e >> 4, ck = e & 15;
            ws[ck][oo] = w[(o0 + oo) * IC + c0 + ck];
        }
#pragma unroll
        for (int i = 0; i < 4; i++) {
            int e = tid + i * 256;
            int ck = e >> 6, pp = e & 63;
            xs[ck][pp] = in[(c0 + ck) * NPOS + p0 + pp];
        }
        __syncthreads();
#pragma unroll
        for (int ck = 0; ck < 16; ck++) {
            float4 xv = *(const float4*)&xs[ck][tx * 4];
            float w0 = ws[ck][ty * 4 + 0];
            float w1 = ws[ck][ty * 4 + 1];
            float w2 = ws[ck][ty * 4 + 2];
            float w3 = ws[ck][ty * 4 + 3];
            acc[0][0] += w0 * xv.x; acc[0][1] += w0 * xv.y; acc[0][2] += w0 * xv.z; acc[0][3] += w0 * xv.w;
            acc[1][0] += w1 * xv.x; acc[1][1] += w1 * xv.y; acc[1][2] += w1 * xv.z; acc[1][3] += w1 * xv.w;
            acc[2][0] += w2 * xv.x; acc[2][1] += w2 * xv.y; acc[2][2] += w2 * xv.z; acc[2][3] += w2 * xv.w;
            acc[3][0] += w3 * xv.x; acc[3][1] += w3 * xv.y; acc[3][2] += w3 * xv.z; acc[3][3] += w3 * xv.w;
        }
    }
#pragma unroll
    for (int i = 0; i < 4; i++)
#pragma unroll
        for (int j = 0; j < 4; j++)
            out[(o0 + ty * 4 + i) * NPOS + p0 + tx * 4 + j] = acc[i][j];
}

// ---------------------------------------------------------------------------
// Depthwise 3x3 conv, padding=1 (cross-correlation), per-channel weights.
// ---------------------------------------------------------------------------
__global__ __launch_bounds__(256) void dw_conv_kernel(
    float* __restrict__ out, const float* __restrict__ in,
    const float* __restrict__ w)
{
    const int o = blockIdx.y;
    const int p = blockIdx.x * 256 + threadIdx.x;
    const int y = p >> 6, x = p & 63;
    const float* ip = in + o * NPOS;
    const float* wp = w + o * 9;
    float acc = 0.f;
#pragma unroll
    for (int dy = 0; dy < 3; dy++) {
        int yy = y + dy - 1;
        if (yy < 0 || yy > 63) continue;
#pragma unroll
        for (int dx = 0; dx < 3; dx++) {
            int xx = x + dx - 1;
            if (xx < 0 || xx > 63) continue;
            acc += wp[dy * 3 + dx] * ip[yy * 64 + xx];
        }
    }
    out[o * NPOS + p] = acc;
}

// ---------------------------------------------------------------------------
// L2-normalize q and k along head_dim(24). Folds QK_SCALE into q.
// One thread per (tensor, head, position). 65536 threads.
// ---------------------------------------------------------------------------
__global__ __launch_bounds__(256) void norm_kernel(float* __restrict__ qkv)
{
    const int g = blockIdx.x * 256 + threadIdx.x;
    const int t = g >> 15;          // 0 = q, 1 = k
    const int rem = g & 32767;
    const int h = rem >> 12;
    const int p = rem & 4095;
    float* base = qkv + (t * 192 + h * 24) * NPOS + p;
    float ss = 0.f;
#pragma unroll
    for (int d = 0; d < 24; d++) {
        float v = base[d * NPOS];
        ss += v * v;
    }
    float inv = 1.0f / fmaxf(sqrtf(ss), 1e-12f);
    if (t == 0) inv *= QK_SCALE;
#pragma unroll
    for (int d = 0; d < 24; d++)
        base[d * NPOS] *= inv;
}

// ---------------------------------------------------------------------------
// Flash attention, fp32. 8 heads, n=4096, d=24.
// Block = 256 threads = 8 warps; each warp owns 2 query rows.
// K/V tiles of 128 keys staged in smem, layout [key][d] with row pad 28
// (28*4B = 112B, 16B-aligned, odd/32 stride -> conflict-free float4 LDS).
// Per-lane online softmax over its key subset, butterfly merge at the end.
// ---------------------------------------------------------------------------
__global__ __launch_bounds__(256) void attn_kernel(
    float* __restrict__ out, const float* __restrict__ qkv)
{
    __shared__ __align__(16) float ks[128 * 28];
    __shared__ __align__(16) float vs[128 * 28];

    const int tid  = threadIdx.x;
    const int lane = tid & 31, wid = tid >> 5;
    const int head = blockIdx.y;
    const int row0 = blockIdx.x * 16 + wid * 2;

    const float* qb = qkv + head * 24 * NPOS;
    const float* kb = qb + 192 * NPOS;
    const float* vb = kb + 192 * NPOS;

    float qv0[24], qv1[24];
#pragma unroll
    for (int d = 0; d < 24; d++) {
        qv0[d] = qb[d * NPOS + row0];
        qv1[d] = qb[d * NPOS + row0 + 1];
    }

    float m0 = -1e30f, m1 = -1e30f, l0 = 0.f, l1 = 0.f;
    float acc0[24] = {}, acc1[24] = {};

    for (int kt = 0; kt < 32; kt++) {
        const int j0 = kt * 128;
        __syncthreads();
#pragma unroll
        for (int i = 0; i < 12; i++) {
            int e = i * 256 + tid;          // 3072 elems per array
            int d = e >> 7, j = e & 127;
            ks[j * 28 + d] = kb[d * NPOS + j0 + j];
            vs[j * 28 + d] = vb[d * NPOS + j0 + j];
        }
        __syncthreads();

#pragma unroll
        for (int jj = 0; jj < 4; jj++) {
            const int j = jj * 32 + lane;
            const float* kp = ks + j * 28;
            float kk[24];
#pragma unroll
            for (int t = 0; t < 6; t++) {
                float4 f = *(const float4*)(kp + 4 * t);
                kk[4 * t + 0] = f.x; kk[4 * t + 1] = f.y;
                kk[4 * t + 2] = f.z; kk[4 * t + 3] = f.w;
            }
            float s0 = 0.f, s1 = 0.f;
#pragma unroll
            for (int d = 0; d < 24; d++) {
                s0 += qv0[d] * kk[d];
                s1 += qv1[d] * kk[d];
            }
            // online softmax, row 0
            float p0;
            if (s0 > m0) {
                float c = __expf(m0 - s0);
                m0 = s0; l0 *= c; p0 = 1.f;
#pragma unroll
                for (int d = 0; d < 24; d++) acc0[d] *= c;
            } else {
                p0 = __expf(s0 - m0);
            }
            l0 += p0;
            // row 1
            float p1;
            if (s1 > m1) {
                float c = __expf(m1 - s1);
                m1 = s1; l1 *= c; p1 = 1.f;
#pragma unroll
                for (int d = 0; d < 24; d++) acc1[d] *= c;
            } else {
                p1 = __expf(s1 - m1);
            }
            l1 += p1;

            const float* vp = vs + j * 28;
#pragma unroll
            for (int t = 0; t < 6; t++) {
                float4 f = *(const float4*)(vp + 4 * t);
                acc0[4 * t + 0] += p0 * f.x; acc1[4 * t + 0] += p1 * f.x;
                acc0[4 * t + 1] += p0 * f.y; acc1[4 * t + 1] += p1 * f.y;
                acc0[4 * t + 2] += p0 * f.z; acc1[4 * t + 2] += p1 * f.z;
                acc0[4 * t + 3] += p0 * f.w; acc1[4 * t + 3] += p1 * f.w;
            }
        }
    }

    // Merge 32 per-lane partial softmaxes (butterfly)
#pragma unroll
    for (int off = 16; off > 0; off >>= 1) {
        {
            float mo = __shfl_xor_sync(0xFFFFFFFFu, m0, off);
            float lo = __shfl_xor_sync(0xFFFFFFFFu, l0, off);
            float mn = fmaxf(m0, mo);
            float cs = __expf(m0 - mn), co = __expf(mo - mn);
            l0 = l0 * cs + lo * co;
#pragma unroll
            for (int d = 0; d < 24; d++) {
                float ao = __shfl_xor_sync(0xFFFFFFFFu, acc0[d], off);
                acc0[d] = acc0[d] * cs + ao * co;
            }
            m0 = mn;
        }
        {
            float mo = __shfl_xor_sync(0xFFFFFFFFu, m1, off);
            float lo = __shfl_xor_sync(0xFFFFFFFFu, l1, off);
            float mn = fmaxf(m1, mo);
            float cs = __expf(m1 - mn), co = __expf(mo - mn);
            l1 = l1 * cs + lo * co;
#pragma unroll
            for (int d = 0; d < 24; d++) {
                float ao = __shfl_xor_sync(0xFFFFFFFFu, acc1[d], off);
                acc1[d] = acc1[d] * cs + ao * co;
            }
            m1 = mn;
        }
    }

    if (lane == 0) {
        float r0 = 1.f / l0, r1 = 1.f / l1;
#pragma unroll
        for (int d = 0; d < 24; d++) {
            out[(head * 24 + d) * NPOS + row0]     = acc0[d] * r0;
            out[(head * 24 + d) * NPOS + row0 + 1] = acc1[d] * r1;
        }
    }
}

// ---------------------------------------------------------------------------
extern "C" void kernel_launch(void* const* d_in, const int* in_sizes, int n_in,
                              void* d_out, int out_size)
{
    const float* x      = (const float*)d_in[0];   // [192][4096]
    const float* w_qkv  = (const float*)d_in[1];   // [576][192]
    const float* w_dw   = (const float*)d_in[2];   // [576][9]
    const float* w_proj = (const float*)d_in[3];   // [192][192]
    float* out = (float*)d_out;                    // [192][4096]

    float *b1, *b2, *at;
    cudaGetSymbolAddress((void**)&b1, g_buf1);
    cudaGetSymbolAddress((void**)&b2, g_buf2);
    cudaGetSymbolAddress((void**)&at, g_attn);

    // 1) qkv 1x1 conv: [576][4096] = W[576][192] @ X[192][4096]
    pw_conv_kernel<<<dim3(NPOS / 64, 576 / 64), 256>>>(b1, x, w_qkv, 192);
    // 2) depthwise 3x3
    dw_conv_kernel<<<dim3(NPOS / 256, 576), 256>>>(b2, b1, w_dw);
    // 3) normalize q (with scale folded) and k
    norm_kernel<<<256, 256>>>(b2);
    // 4) attention
    attn_kernel<<<dim3(NPOS / 16, 8), 256>>>(at, b2);
    // 5) projection 1x1 conv
    pw_conv_kernel<<<dim3(NPOS / 64, 192 / 64), 256>>>(out, at, w_proj, 192);
}

// round 2
// speedup vs baseline: 1.9732x; 1.9732x over previous
#include <cuda_runtime.h>
#include <math.h>

#define NPOS 4096
#define QK_SCALE 0.2041241452319315f  /* 24^-0.5 */
#define KSPLIT 4

// Scratch (device globals — no allocation allowed)
__device__ float g_buf1[576 * NPOS];            // qkv after 1x1 conv
__device__ float g_buf2[576 * NPOS];            // qkv after dw conv (q,k normalized in place)
__device__ float g_attn[192 * NPOS];            // attention output, [c][p]
__device__ float g_pacc[8 * KSPLIT * 24 * NPOS];// split-K partial acc
__device__ float g_pl[8 * KSPLIT * NPOS];       // split-K partial l

typedef unsigned long long u64t;

__device__ __forceinline__ u64t ffma2(u64t a, u64t b, u64t c) {
    u64t d;
    asm("fma.rn.f32x2 %0, %1, %2, %3;" : "=l"(d) : "l"(a), "l"(b), "l"(c));
    return d;
}
__device__ __forceinline__ u64t pack2(float lo, float hi) {
    u64t r; asm("mov.b64 %0, {%1, %2};" : "=l"(r) : "f"(lo), "f"(hi)); return r;
}
__device__ __forceinline__ float2 unpack2(u64t v) {
    float2 f; asm("mov.b64 {%0, %1}, %2;" : "=f"(f.x), "=f"(f.y) : "l"(v)); return f;
}

// ---------------------------------------------------------------------------
// Pointwise (1x1) conv as GEMM: out[o][p] = sum_c w[o*IC+c] * in[c][p]
// ---------------------------------------------------------------------------
__global__ __launch_bounds__(256) void pw_conv_kernel(
    float* __restrict__ out, const float* __restrict__ in,
    const float* __restrict__ w, int IC)
{
    __shared__ __align__(16) float ws[16][65];
    __shared__ __align__(16) float xs[16][64];

    const int tid = threadIdx.x;
    const int tx = tid & 15, ty = tid >> 4;
    const int p0 = blockIdx.x * 64;
    const int o0 = blockIdx.y * 64;

    float acc[4][4] = {};

    for (int c0 = 0; c0 < IC; c0 += 16) {
        __syncthreads();
#pragma unroll
        for (int i = 0; i < 4; i++) {
            int e = tid + i * 256;
            int oo = e >> 4, ck = e & 15;
            ws[ck][oo] = w[(o0 + oo) * IC + c0 + ck];
        }
#pragma unroll
        for (int i = 0; i < 4; i++) {
            int e = tid + i * 256;
            int ck = e >> 6, pp = e & 63;
            xs[ck][pp] = in[(c0 + ck) * NPOS + p0 + pp];
        }
        __syncthreads();
#pragma unroll
        for (int ck = 0; ck < 16; ck++) {
            float4 xv = *(const float4*)&xs[ck][tx * 4];
            float w0 = ws[ck][ty * 4 + 0];
            float w1 = ws[ck][ty * 4 + 1];
            float w2 = ws[ck][ty * 4 + 2];
            float w3 = ws[ck][ty * 4 + 3];
            acc[0][0] += w0 * xv.x; acc[0][1] += w0 * xv.y; acc[0][2] += w0 * xv.z; acc[0][3] += w0 * xv.w;
            acc[1][0] += w1 * xv.x; acc[1][1] += w1 * xv.y; acc[1][2] += w1 * xv.z; acc[1][3] += w1 * xv.w;
            acc[2][0] += w2 * xv.x; acc[2][1] += w2 * xv.y; acc[2][2] += w2 * xv.z; acc[2][3] += w2 * xv.w;
            acc[3][0] += w3 * xv.x; acc[3][1] += w3 * xv.y; acc[3][2] += w3 * xv.z; acc[3][3] += w3 * xv.w;
        }
    }
#pragma unroll
    for (int i = 0; i < 4; i++)
#pragma unroll
        for (int j = 0; j < 4; j++)
            out[(o0 + ty * 4 + i) * NPOS + p0 + tx * 4 + j] = acc[i][j];
}

// ---------------------------------------------------------------------------
// Depthwise 3x3 conv, padding=1
// ---------------------------------------------------------------------------
__global__ __launch_bounds__(256) void dw_conv_kernel(
    float* __restrict__ out, const float* __restrict__ in,
    const float* __restrict__ w)
{
    const int o = blockIdx.y;
    const int p = blockIdx.x * 256 + threadIdx.x;
    const int y = p >> 6, x = p & 63;
    const float* ip = in + o * NPOS;
    const float* wp = w + o * 9;
    float acc = 0.f;
#pragma unroll
    for (int dy = 0; dy < 3; dy++) {
        int yy = y + dy - 1;
        if (yy < 0 || yy > 63) continue;
#pragma unroll
        for (int dx = 0; dx < 3; dx++) {
            int xx = x + dx - 1;
            if (xx < 0 || xx > 63) continue;
            acc += wp[dy * 3 + dx] * ip[yy * 64 + xx];
        }
    }
    out[o * NPOS + p] = acc;
}

// ---------------------------------------------------------------------------
// L2-normalize q and k along head_dim(24); fold QK_SCALE into q.
// ---------------------------------------------------------------------------
__global__ __launch_bounds__(256) void norm_kernel(float* __restrict__ qkv)
{
    const int g = blockIdx.x * 256 + threadIdx.x;
    const int t = g >> 15;
    const int rem = g & 32767;
    const int h = rem >> 12;
    const int p = rem & 4095;
    float* base = qkv + (t * 192 + h * 24) * NPOS + p;
    float ss = 0.f;
#pragma unroll
    for (int d = 0; d < 24; d++) {
        float v = base[d * NPOS];
        ss += v * v;
    }
    float inv = 1.0f / fmaxf(sqrtf(ss), 1e-12f);
    if (t == 0) inv *= QK_SCALE;
#pragma unroll
    for (int d = 0; d < 24; d++)
        base[d * NPOS] *= inv;
}

// ---------------------------------------------------------------------------
// Flash-style attention, fp32 with packed f32x2 FMA.
// Each lane owns ONE query row => all K/V smem reads are warp broadcasts.
// Scores bounded in [-0.205, 0.205] (q,k unit-norm, scale folded) => no
// max-tracking; split-K partials combine by simple addition.
// Block: 256 thr (8 warps) = 256 rows. Grid: (16 row tiles, KSPLIT, 8 heads).
// ---------------------------------------------------------------------------
__global__ __launch_bounds__(256, 2) void attn_kernel(
    float* __restrict__ pacc, float* __restrict__ pl,
    const float* __restrict__ qkv)
{
    __shared__ __align__(16) float ks[128 * 24];
    __shared__ __align__(16) float vs[128 * 24];

    const int tid   = threadIdx.x;
    const int head  = blockIdx.z;
    const int split = blockIdx.y;
    const int row   = blockIdx.x * 256 + tid;

    const float* qb = qkv + head * 24 * NPOS;
    const float* kb = qb + 192 * NPOS;
    const float* vb = kb + 192 * NPOS;

    // q packed: 12 x f32x2
    u64t q2[12];
#pragma unroll
    for (int i = 0; i < 12; i++)
        q2[i] = pack2(qb[(2 * i) * NPOS + row], qb[(2 * i + 1) * NPOS + row]);

    u64t acc2[12];
#pragma unroll
    for (int i = 0; i < 12; i++) acc2[i] = 0ull;
    float l = 0.f;

    const int kbase = split * (NPOS / KSPLIT);

    for (int kt = 0; kt < (NPOS / KSPLIT) / 128; kt++) {
        const int j0 = kbase + kt * 128;
        __syncthreads();
#pragma unroll
        for (int i = 0; i < 12; i++) {
            int e = i * 256 + tid;            // 3072 elems per array
            int d = e >> 7, j = e & 127;
            ks[j * 24 + d] = kb[d * NPOS + j0 + j];
            vs[j * 24 + d] = vb[d * NPOS + j0 + j];
        }
        __syncthreads();

#pragma unroll 4
        for (int j = 0; j < 128; j++) {
            const ulonglong2* kp = (const ulonglong2*)(ks + j * 24);
            ulonglong2 ka = kp[0], kc = kp[1], ke = kp[2];
            u64t sa = 0ull, sb = 0ull;
            sa = ffma2(q2[0],  ka.x, sa);  sb = ffma2(q2[1],  ka.y, sb);
            sa = ffma2(q2[2],  kc.x, sa);  sb = ffma2(q2[3],  kc.y, sb);
            sa = ffma2(q2[4],  ke.x, sa);  sb = ffma2(q2[5],  ke.y, sb);
            const ulonglong2* kp2 = kp + 3;
            ulonglong2 kg = kp2[0], ki = kp2[1], kk = kp2[2];
            sa = ffma2(q2[6],  kg.x, sa);  sb = ffma2(q2[7],  kg.y, sb);
            sa = ffma2(q2[8],  ki.x, sa);  sb = ffma2(q2[9],  ki.y, sb);
            sa = ffma2(q2[10], kk.x, sa);  sb = ffma2(q2[11], kk.y, sb);

            float2 fa = unpack2(sa), fb = unpack2(sb);
            float s = (fa.x + fa.y) + (fb.x + fb.y);
            float p = __expf(s);          // s in [-0.205, 0.205] — safe
            l += p;
            u64t p2 = pack2(p, p);

            const ulonglong2* vp = (const ulonglong2*)(vs + j * 24);
            ulonglong2 va = vp[0], vc = vp[1], ve = vp[2];
            acc2[0] = ffma2(p2, va.x, acc2[0]);
            acc2[1] = ffma2(p2, va.y, acc2[1]);
            acc2[2] = ffma2(p2, vc.x, acc2[2]);
            acc2[3] = ffma2(p2, vc.y, acc2[3]);
            acc2[4] = ffma2(p2, ve.x, acc2[4]);
            acc2[5] = ffma2(p2, ve.y, acc2[5]);
            const ulonglong2* vp2 = vp + 3;
            ulonglong2 vg = vp2[0], vi = vp2[1], vk = vp2[2];
            acc2[6]  = ffma2(p2, vg.x, acc2[6]);
            acc2[7]  = ffma2(p2, vg.y, acc2[7]);
            acc2[8]  = ffma2(p2, vi.x, acc2[8]);
            acc2[9]  = ffma2(p2, vi.y, acc2[9]);
            acc2[10] = ffma2(p2, vk.x, acc2[10]);
            acc2[11] = ffma2(p2, vk.y, acc2[11]);
        }
    }

    // Write partials (coalesced: lanes differ by row)
    float* pa = pacc + ((head * KSPLIT + split) * 24) * NPOS + row;
#pragma unroll
    for (int i = 0; i < 12; i++) {
        float2 f = unpack2(acc2[i]);
        pa[(2 * i) * NPOS]     = f.x;
        pa[(2 * i + 1) * NPOS] = f.y;
    }
    pl[(head * KSPLIT + split) * NPOS + row] = l;
}

// ---------------------------------------------------------------------------
// Combine split-K partials (plain sums — no max bookkeeping needed).
// ---------------------------------------------------------------------------
__global__ __launch_bounds__(256) void combine_kernel(
    float* __restrict__ out, const float* __restrict__ pacc,
    const float* __restrict__ pl)
{
    const int g = blockIdx.x * 256 + threadIdx.x;   // 32768 = 8 heads * 4096 rows
    const int head = g >> 12, row = g & 4095;
    float l = 0.f;
#pragma unroll
    for (int s = 0; s < KSPLIT; s++)
        l += pl[(head * KSPLIT + s) * NPOS + row];
    const float inv = 1.0f / l;
#pragma unroll
    for (int d = 0; d < 24; d++) {
        float a = 0.f;
#pragma unroll
        for (int s = 0; s < KSPLIT; s++)
            a += pacc[((head * KSPLIT + s) * 24 + d) * NPOS + row];
        out[(head * 24 + d) * NPOS + row] = a * inv;
    }
}

// ---------------------------------------------------------------------------
extern "C" void kernel_launch(void* const* d_in, const int* in_sizes, int n_in,
                              void* d_out, int out_size)
{
    const float* x      = (const float*)d_in[0];
    const float* w_qkv  = (const float*)d_in[1];
    const float* w_dw   = (const float*)d_in[2];
    const float* w_proj = (const float*)d_in[3];
    float* out = (float*)d_out;

    float *b1, *b2, *at, *pa, *plv;
    cudaGetSymbolAddress((void**)&b1, g_buf1);
    cudaGetSymbolAddress((void**)&b2, g_buf2);
    cudaGetSymbolAddress((void**)&at, g_attn);
    cudaGetSymbolAddress((void**)&pa, g_pacc);
    cudaGetSymbolAddress((void**)&plv, g_pl);

    pw_conv_kernel<<<dim3(NPOS / 64, 576 / 64), 256>>>(b1, x, w_qkv, 192);
    dw_conv_kernel<<<dim3(NPOS / 256, 576), 256>>>(b2, b1, w_dw);
    norm_kernel<<<256, 256>>>(b2);
    attn_kernel<<<dim3(NPOS / 256, KSPLIT, 8), 256>>>(pa, plv, b2);
    combine_kernel<<<128, 256>>>(at, pa, plv);
    pw_conv_kernel<<<dim3(NPOS / 64, 192 / 64), 256>>>(out, at, w_proj, 192);
}

// round 3
// speedup vs baseline: 2.4289x; 1.2309x over previous
#include <cuda_runtime.h>
#include <math.h>

#define NPOS 4096
#define QK_SCALE 0.2041241452319315f  /* 24^-0.5 */
#define KSPLIT 4

// Scratch (device globals — no allocation allowed)
__device__ float g_buf1[576 * NPOS];            // qkv after 1x1 conv
__device__ float g_buf2[576 * NPOS];            // qkv after dw conv (q,k normalized in place)
__device__ float g_attn[192 * NPOS];            // attention output, [c][p]
__device__ float g_pacc[8 * KSPLIT * 24 * NPOS];// split-K partial acc
__device__ float g_pl[8 * KSPLIT * NPOS];       // split-K partial l

typedef unsigned long long u64t;

__device__ __forceinline__ u64t ffma2(u64t a, u64t b, u64t c) {
    u64t d;
    asm("fma.rn.f32x2 %0, %1, %2, %3;" : "=l"(d) : "l"(a), "l"(b), "l"(c));
    return d;
}
__device__ __forceinline__ u64t pack2(float lo, float hi) {
    u64t r; asm("mov.b64 %0, {%1, %2};" : "=l"(r) : "f"(lo), "f"(hi)); return r;
}
__device__ __forceinline__ float2 unpack2(u64t v) {
    float2 f; asm("mov.b64 {%0, %1}, %2;" : "=f"(f.x), "=f"(f.y) : "l"(v)); return f;
}

// ---------------------------------------------------------------------------
// Pointwise (1x1) conv as GEMM: out[o][p] = sum_c w[o*IC+c] * in[c][p]
// ---------------------------------------------------------------------------
__global__ __launch_bounds__(256) void pw_conv_kernel(
    float* __restrict__ out, const float* __restrict__ in,
    const float* __restrict__ w, int IC)
{
    __shared__ __align__(16) float ws[16][65];
    __shared__ __align__(16) float xs[16][64];

    const int tid = threadIdx.x;
    const int tx = tid & 15, ty = tid >> 4;
    const int p0 = blockIdx.x * 64;
    const int o0 = blockIdx.y * 64;

    float acc[4][4] = {};

    for (int c0 = 0; c0 < IC; c0 += 16) {
        __syncthreads();
#pragma unroll
        for (int i = 0; i < 4; i++) {
            int e = tid + i * 256;
            int oo = e >> 4, ck = e & 15;
            ws[ck][oo] = w[(o0 + oo) * IC + c0 + ck];
        }
#pragma unroll
        for (int i = 0; i < 4; i++) {
            int e = tid + i * 256;
            int ck = e >> 6, pp = e & 63;
            xs[ck][pp] = in[(c0 + ck) * NPOS + p0 + pp];
        }
        __syncthreads();
#pragma unroll
        for (int ck = 0; ck < 16; ck++) {
            float4 xv = *(const float4*)&xs[ck][tx * 4];
            float w0 = ws[ck][ty * 4 + 0];
            float w1 = ws[ck][ty * 4 + 1];
            float w2 = ws[ck][ty * 4 + 2];
            float w3 = ws[ck][ty * 4 + 3];
            acc[0][0] += w0 * xv.x; acc[0][1] += w0 * xv.y; acc[0][2] += w0 * xv.z; acc[0][3] += w0 * xv.w;
            acc[1][0] += w1 * xv.x; acc[1][1] += w1 * xv.y; acc[1][2] += w1 * xv.z; acc[1][3] += w1 * xv.w;
            acc[2][0] += w2 * xv.x; acc[2][1] += w2 * xv.y; acc[2][2] += w2 * xv.z; acc[2][3] += w2 * xv.w;
            acc[3][0] += w3 * xv.x; acc[3][1] += w3 * xv.y; acc[3][2] += w3 * xv.z; acc[3][3] += w3 * xv.w;
        }
    }
#pragma unroll
    for (int i = 0; i < 4; i++)
#pragma unroll
        for (int j = 0; j < 4; j++)
            out[(o0 + ty * 4 + i) * NPOS + p0 + tx * 4 + j] = acc[i][j];
}

// ---------------------------------------------------------------------------
// Depthwise 3x3 conv, padding=1
// ---------------------------------------------------------------------------
__global__ __launch_bounds__(256) void dw_conv_kernel(
    float* __restrict__ out, const float* __restrict__ in,
    const float* __restrict__ w)
{
    const int o = blockIdx.y;
    const int p = blockIdx.x * 256 + threadIdx.x;
    const int y = p >> 6, x = p & 63;
    const float* ip = in + o * NPOS;
    const float* wp = w + o * 9;
    float acc = 0.f;
#pragma unroll
    for (int dy = 0; dy < 3; dy++) {
        int yy = y + dy - 1;
        if (yy < 0 || yy > 63) continue;
#pragma unroll
        for (int dx = 0; dx < 3; dx++) {
            int xx = x + dx - 1;
            if (xx < 0 || xx > 63) continue;
            acc += wp[dy * 3 + dx] * ip[yy * 64 + xx];
        }
    }
    out[o * NPOS + p] = acc;
}

// ---------------------------------------------------------------------------
// L2-normalize q and k along head_dim(24); fold QK_SCALE into q.
// ---------------------------------------------------------------------------
__global__ __launch_bounds__(256) void norm_kernel(float* __restrict__ qkv)
{
    const int g = blockIdx.x * 256 + threadIdx.x;
    const int t = g >> 15;
    const int rem = g & 32767;
    const int h = rem >> 12;
    const int p = rem & 4095;
    float* base = qkv + (t * 192 + h * 24) * NPOS + p;
    float ss = 0.f;
#pragma unroll
    for (int d = 0; d < 24; d++) {
        float v = base[d * NPOS];
        ss += v * v;
    }
    float inv = 1.0f / fmaxf(sqrtf(ss), 1e-12f);
    if (t == 0) inv *= QK_SCALE;
#pragma unroll
    for (int d = 0; d < 24; d++)
        base[d * NPOS] *= inv;
}

// ---------------------------------------------------------------------------
// Flash-style attention, fp32 packed-f32x2, TWO query rows per lane.
// Per key per warp: 12 LDS.128 vs 48 FFMA2 -> fma-bound.
// Scores bounded (unit-norm q,k; scale folded) => no max-tracking; split-K
// partials combine by plain addition.
// Block: 256 thr covers 512 rows (tid and tid+256). Grid: (8, KSPLIT, 8).
// ---------------------------------------------------------------------------
__global__ __launch_bounds__(256, 2) void attn_kernel(
    float* __restrict__ pacc, float* __restrict__ pl,
    const float* __restrict__ qkv)
{
    __shared__ __align__(16) float ks[128 * 24];
    __shared__ __align__(16) float vs[128 * 24];

    const int tid   = threadIdx.x;
    const int head  = blockIdx.z;
    const int split = blockIdx.y;
    const int r0    = blockIdx.x * 512 + tid;
    const int r1    = r0 + 256;

    const float* qb = qkv + head * 24 * NPOS;
    const float* kb = qb + 192 * NPOS;
    const float* vb = kb + 192 * NPOS;

    u64t q0[12], q1[12];
#pragma unroll
    for (int i = 0; i < 12; i++) {
        q0[i] = pack2(qb[(2 * i) * NPOS + r0], qb[(2 * i + 1) * NPOS + r0]);
        q1[i] = pack2(qb[(2 * i) * NPOS + r1], qb[(2 * i + 1) * NPOS + r1]);
    }

    u64t acc0[12], acc1[12];
#pragma unroll
    for (int i = 0; i < 12; i++) { acc0[i] = 0ull; acc1[i] = 0ull; }
    float l0 = 0.f, l1 = 0.f;

    const int kbase = split * (NPOS / KSPLIT);

    for (int kt = 0; kt < (NPOS / KSPLIT) / 128; kt++) {
        const int j0 = kbase + kt * 128;
        __syncthreads();
#pragma unroll
        for (int i = 0; i < 12; i++) {
            int e = i * 256 + tid;            // 3072 elems per array
            int d = e >> 7, j = e & 127;
            ks[j * 24 + d] = kb[d * NPOS + j0 + j];
            vs[j * 24 + d] = vb[d * NPOS + j0 + j];
        }
        __syncthreads();

#pragma unroll 2
        for (int j = 0; j < 128; j++) {
            const ulonglong2* kp = (const ulonglong2*)(ks + j * 24);
            u64t sa0 = 0ull, sb0 = 0ull, sa1 = 0ull, sb1 = 0ull;
            {
                ulonglong2 t0 = kp[0], t1 = kp[1], t2 = kp[2];
                sa0 = ffma2(q0[0], t0.x, sa0);  sa1 = ffma2(q1[0], t0.x, sa1);
                sb0 = ffma2(q0[1], t0.y, sb0);  sb1 = ffma2(q1[1], t0.y, sb1);
                sa0 = ffma2(q0[2], t1.x, sa0);  sa1 = ffma2(q1[2], t1.x, sa1);
                sb0 = ffma2(q0[3], t1.y, sb0);  sb1 = ffma2(q1[3], t1.y, sb1);
                sa0 = ffma2(q0[4], t2.x, sa0);  sa1 = ffma2(q1[4], t2.x, sa1);
                sb0 = ffma2(q0[5], t2.y, sb0);  sb1 = ffma2(q1[5], t2.y, sb1);
            }
            {
                ulonglong2 t3 = kp[3], t4 = kp[4], t5 = kp[5];
                sa0 = ffma2(q0[6],  t3.x, sa0);  sa1 = ffma2(q1[6],  t3.x, sa1);
                sb0 = ffma2(q0[7],  t3.y, sb0);  sb1 = ffma2(q1[7],  t3.y, sb1);
                sa0 = ffma2(q0[8],  t4.x, sa0);  sa1 = ffma2(q1[8],  t4.x, sa1);
                sb0 = ffma2(q0[9],  t4.y, sb0);  sb1 = ffma2(q1[9],  t4.y, sb1);
                sa0 = ffma2(q0[10], t5.x, sa0);  sa1 = ffma2(q1[10], t5.x, sa1);
                sb0 = ffma2(q0[11], t5.y, sb0);  sb1 = ffma2(q1[11], t5.y, sb1);
            }

            float2 fa0 = unpack2(sa0), fb0 = unpack2(sb0);
            float2 fa1 = unpack2(sa1), fb1 = unpack2(sb1);
            float s0 = (fa0.x + fa0.y) + (fb0.x + fb0.y);
            float s1 = (fa1.x + fa1.y) + (fb1.x + fb1.y);
            float p0 = __expf(s0);        // bounded scores — safe
            float p1 = __expf(s1);
            l0 += p0;
            l1 += p1;
            u64t p20 = pack2(p0, p0);
            u64t p21 = pack2(p1, p1);

            const ulonglong2* vp = (const ulonglong2*)(vs + j * 24);
            {
                ulonglong2 t0 = vp[0], t1 = vp[1], t2 = vp[2];
                acc0[0] = ffma2(p20, t0.x, acc0[0]);  acc1[0] = ffma2(p21, t0.x, acc1[0]);
                acc0[1] = ffma2(p20, t0.y, acc0[1]);  acc1[1] = ffma2(p21, t0.y, acc1[1]);
                acc0[2] = ffma2(p20, t1.x, acc0[2]);  acc1[2] = ffma2(p21, t1.x, acc1[2]);
                acc0[3] = ffma2(p20, t1.y, acc0[3]);  acc1[3] = ffma2(p21, t1.y, acc1[3]);
                acc0[4] = ffma2(p20, t2.x, acc0[4]);  acc1[4] = ffma2(p21, t2.x, acc1[4]);
                acc0[5] = ffma2(p20, t2.y, acc0[5]);  acc1[5] = ffma2(p21, t2.y, acc1[5]);
            }
            {
                ulonglong2 t3 = vp[3], t4 = vp[4], t5 = vp[5];
                acc0[6]  = ffma2(p20, t3.x, acc0[6]);   acc1[6]  = ffma2(p21, t3.x, acc1[6]);
                acc0[7]  = ffma2(p20, t3.y, acc0[7]);   acc1[7]  = ffma2(p21, t3.y, acc1[7]);
                acc0[8]  = ffma2(p20, t4.x, acc0[8]);   acc1[8]  = ffma2(p21, t4.x, acc1[8]);
                acc0[9]  = ffma2(p20, t4.y, acc0[9]);   acc1[9]  = ffma2(p21, t4.y, acc1[9]);
                acc0[10] = ffma2(p20, t5.x, acc0[10]);  acc1[10] = ffma2(p21, t5.x, acc1[10]);
                acc0[11] = ffma2(p20, t5.y, acc0[11]);  acc1[11] = ffma2(p21, t5.y, acc1[11]);
            }
        }
    }

    // Write partials (coalesced: lanes differ by row)
    float* pa0 = pacc + ((head * KSPLIT + split) * 24) * NPOS + r0;
    float* pa1 = pacc + ((head * KSPLIT + split) * 24) * NPOS + r1;
#pragma unroll
    for (int i = 0; i < 12; i++) {
        float2 f0 = unpack2(acc0[i]);
        float2 f1 = unpack2(acc1[i]);
        pa0[(2 * i) * NPOS]     = f0.x;
        pa0[(2 * i + 1) * NPOS] = f0.y;
        pa1[(2 * i) * NPOS]     = f1.x;
        pa1[(2 * i + 1) * NPOS] = f1.y;
    }
    pl[(head * KSPLIT + split) * NPOS + r0] = l0;
    pl[(head * KSPLIT + split) * NPOS + r1] = l1;
}

// ---------------------------------------------------------------------------
// Combine split-K partials (plain sums — no max bookkeeping needed).
// ---------------------------------------------------------------------------
__global__ __launch_bounds__(256) void combine_kernel(
    float* __restrict__ out, const float* __restrict__ pacc,
    const float* __restrict__ pl)
{
    const int g = blockIdx.x * 256 + threadIdx.x;   // 32768 = 8 heads * 4096 rows
    const int head = g >> 12, row = g & 4095;
    float l = 0.f;
#pragma unroll
    for (int s = 0; s < KSPLIT; s++)
        l += pl[(head * KSPLIT + s) * NPOS + row];
    const float inv = 1.0f / l;
#pragma unroll
    for (int d = 0; d < 24; d++) {
        float a = 0.f;
#pragma unroll
        for (int s = 0; s < KSPLIT; s++)
            a += pacc[((head * KSPLIT + s) * 24 + d) * NPOS + row];
        out[(head * 24 + d) * NPOS + row] = a * inv;
    }
}

// ---------------------------------------------------------------------------
extern "C" void kernel_launch(void* const* d_in, const int* in_sizes, int n_in,
                              void* d_out, int out_size)
{
    const float* x      = (const float*)d_in[0];
    const float* w_qkv  = (const float*)d_in[1];
    const float* w_dw   = (const float*)d_in[2];
    const float* w_proj = (const float*)d_in[3];
    float* out = (float*)d_out;

    float *b1, *b2, *at, *pa, *plv;
    cudaGetSymbolAddress((void**)&b1, g_buf1);
    cudaGetSymbolAddress((void**)&b2, g_buf2);
    cudaGetSymbolAddress((void**)&at, g_attn);
    cudaGetSymbolAddress((void**)&pa, g_pacc);
    cudaGetSymbolAddress((void**)&plv, g_pl);

    pw_conv_kernel<<<dim3(NPOS / 64, 576 / 64), 256>>>(b1, x, w_qkv, 192);
    dw_conv_kernel<<<dim3(NPOS / 256, 576), 256>>>(b2, b1, w_dw);
    norm_kernel<<<256, 256>>>(b2);
    attn_kernel<<<dim3(NPOS / 512, KSPLIT, 8), 256>>>(pa, plv, b2);
    combine_kernel<<<128, 256>>>(at, pa, plv);
    pw_conv_kernel<<<dim3(NPOS / 64, 192 / 64), 256>>>(out, at, w_proj, 192);
}